// round 7
// baseline (speedup 1.0000x reference)
#include <cuda_runtime.h>
#include <cuda_bf16.h>

#define NN 100000
#define EE 1600000
#define NT 391            // node tiles of 256

#define FMA_F32X2(d, a, b, c) \
    asm("fma.rn.f32x2 %0, %1, %2, %3;" : "=l"(d) : "l"(a), "l"(b), "l"(c))
#define PACK_DUP_F32X2(out, f) do { \
    unsigned _u = __float_as_uint(f); \
    asm("mov.b64 %0, {%1, %1};" : "=l"(out) : "r"(_u)); } while (0)
#define UNPACK_F32X2(lo, hi, in) \
    asm("mov.b64 {%0, %1}, %2;" : "=f"(lo), "=f"(hi) : "l"(in))

// 2 nodes x one ulonglong2 weight pair -> 4 FFMA2
#define STEP2(acc, J, w, h0, h1) do { \
    FMA_F32X2(acc[(J)],     h0, (w).x, acc[(J)]); \
    FMA_F32X2(acc[(J)+1],   h0, (w).y, acc[(J)+1]); \
    FMA_F32X2(acc[8+(J)],   h1, (w).x, acc[8+(J)]); \
    FMA_F32X2(acc[8+(J)+1], h1, (w).y, acc[8+(J)+1]); } while (0)

// ---- device scratch (no allocation) ----
__device__ float g_At[3 * 64 * 64];             // composed head weights [h][l][i]
__device__ float g_bh[3 * 64];                  // composed head biases
__device__ float g_u1[64];                      // W2^T Ws^T wsc
__device__ float g_c1;
__device__ __nv_bfloat16 g_kh[(size_t)NN * 64];
__device__ __nv_bfloat16 g_qh[(size_t)NN * 64];
__device__ __nv_bfloat16 g_vh[(size_t)NN * 64];

// ---------------- prologue: compose weights ----------------
__global__ void prec1(const float* __restrict__ W2, const float* __restrict__ b2,
                      const float* __restrict__ Wk, const float* __restrict__ bk,
                      const float* __restrict__ Wq, const float* __restrict__ bq,
                      const float* __restrict__ Wv, const float* __restrict__ bv,
                      const float* __restrict__ Ws, const float* __restrict__ b_gate,
                      const float* __restrict__ Wsc, const float* __restrict__ bsc)
{
    int id = blockIdx.x * 256 + threadIdx.x;
    if (id < 12288) {
        int head = id >> 12, rem = id & 4095;
        int l = rem >> 6, i = rem & 63;
        const float* Wh = head == 0 ? Wk : head == 1 ? Wq : Wv;
        float s = 0.f;
        for (int j = 0; j < 64; j++) s = fmaf(Wh[i * 64 + j], W2[j * 64 + l], s);
        if (head == 2) s *= Wsc[i];
        g_At[head * 4096 + l * 64 + i] = s;
    } else if (id < 12352) {
        int i = id - 12288;
        float sk = bk[i], sq = bq[i], sv = bv[i];
        for (int j = 0; j < 64; j++) {
            sk = fmaf(Wk[i * 64 + j], b2[j], sk);
            sq = fmaf(Wq[i * 64 + j], b2[j], sq);
            sv = fmaf(Wv[i * 64 + j], b2[j], sv);
        }
        g_bh[i] = sk; g_bh[64 + i] = sq; g_bh[128 + i] = sv * Wsc[i];
        float u1 = 0.f;
        for (int l = 0; l < 64; l++) {
            float ul = 0.f;
            for (int j = 0; j < 64; j++) ul = fmaf(Wsc[j], Ws[j * 64 + l], ul);
            u1 = fmaf(ul, W2[l * 64 + i], u1);
        }
        g_u1[i] = u1;
        if (i == 0) {
            float c = bsc[0];
            for (int j = 0; j < 64; j++) c = fmaf(Wsc[j], b_gate[j], c);
            for (int l = 0; l < 64; l++) {
                float ul = 0.f;
                for (int j = 0; j < 64; j++) ul = fmaf(Wsc[j], Ws[j * 64 + l], ul);
                c = fmaf(ul, b2[l], c);
            }
            g_c1 = c;
        }
    }
}

__device__ __forceinline__ unsigned pack_bf2(float a, float b) {
    __nv_bfloat162 h = __floats2bfloat162_rn(a, b);
    return *reinterpret_cast<unsigned*>(&h);
}

// ---------------- fused persistent node kernel ----------------
// grid=148, 512 thr, 1 block/SM. Weights staged once; h1 stays in smem.
// thread: fh = tid>>7 (16-feat group), np = tid&127; nodes {np, np+128} of a 256-node tile.
__global__ __launch_bounds__(512, 1)
void node_fused(const float* __restrict__ x,
                const float* __restrict__ W1, const float* __restrict__ b1,
                float* __restrict__ out)
{
    extern __shared__ float sm[];
    float* at  = sm;               // 12288
    float* w1t = at + 12288;       // 8192 : [i=128][j=64]
    float* bb  = w1t + 8192;       // 320 : b1(64) | bh(192) | u1(64)
    float* xs  = bb + 320;         // 32 * 257
    float* hs  = xs + 32 * 257;    // 64 * 256

    const int tid = threadIdx.x;

    // ---- stage all weights ONCE ----
    for (int idx = tid; idx < 8192; idx += 512) {
        int j = idx >> 7, i = idx & 127;
        w1t[i * 64 + j] = W1[idx];
    }
    for (int idx = tid; idx < 3072; idx += 512)
        ((float4*)at)[idx] = ((const float4*)g_At)[idx];
    if (tid < 64)       bb[tid] = b1[tid];
    else if (tid < 256) bb[tid] = g_bh[tid - 64];
    else if (tid < 320) bb[tid] = g_u1[tid - 256];
    const float c1 = g_c1;
    __syncthreads();

    const int fh = tid >> 7;       // 0..3
    const int np = tid & 127;      // 0..127

    for (int tile = blockIdx.x; tile < NT; tile += gridDim.x) {
        const int base = tile * 256;

        // ---- layer 1 ----
        unsigned long long acc2[16];
        {
            const unsigned long long* bp = (const unsigned long long*)(bb + fh * 16);
            #pragma unroll
            for (int k = 0; k < 2; k++)
                #pragma unroll
                for (int j = 0; j < 8; j++) acc2[k * 8 + j] = bp[j];
        }

        for (int c = 0; c < 4; c++) {
            __syncthreads();   // xs free (and, at c==0, hs readers of prev tile done)
            #pragma unroll
            for (int idx = tid; idx < 2048; idx += 512) {
                int n = idx >> 3, i4 = idx & 7;
                int nn = base + n;
                float4 v = (nn < NN) ? ((const float4*)x)[(size_t)nn * 32 + c * 8 + i4]
                                     : make_float4(0.f, 0.f, 0.f, 0.f);
                xs[(i4 * 4 + 0) * 257 + n] = v.x;
                xs[(i4 * 4 + 1) * 257 + n] = v.y;
                xs[(i4 * 4 + 2) * 257 + n] = v.z;
                xs[(i4 * 4 + 3) * 257 + n] = v.w;
            }
            __syncthreads();
            const float* wbase = w1t + c * 2048 + fh * 16;
            for (int i = 0; i < 32; i++) {
                const float* xr = xs + i * 257 + np;
                unsigned long long h0, h1;
                PACK_DUP_F32X2(h0, xr[0]);
                PACK_DUP_F32X2(h1, xr[128]);
                const ulonglong2* wr = (const ulonglong2*)(wbase + i * 64);
                { ulonglong2 w = wr[0]; STEP2(acc2, 0, w, h0, h1); }
                { ulonglong2 w = wr[1]; STEP2(acc2, 2, w, h0, h1); }
                { ulonglong2 w = wr[2]; STEP2(acc2, 4, w, h0, h1); }
                { ulonglong2 w = wr[3]; STEP2(acc2, 6, w, h0, h1); }
            }
        }

        // ---- h1 -> smem ----
        #pragma unroll
        for (int k = 0; k < 2; k++) {
            int n = np + 128 * k;
            #pragma unroll
            for (int j = 0; j < 8; j++) {
                float lo, hi;
                UNPACK_F32X2(lo, hi, acc2[k * 8 + j]);
                hs[(fh * 16 + 2 * j + 0) * 256 + n] = fmaxf(lo, 0.f);
                hs[(fh * 16 + 2 * j + 1) * 256 + n] = fmaxf(hi, 0.f);
            }
        }
        __syncthreads();

        // ---- score (warp-uniform: fh==0 group) ----
        if (fh == 0) {
            float s0 = c1, s1 = c1;
            #pragma unroll 4
            for (int l = 0; l < 64; l++) {
                float ul = bb[256 + l];
                const float* hr = hs + l * 256 + np;
                s0 = fmaf(hr[0],   ul, s0);
                s1 = fmaf(hr[128], ul, s1);
            }
            if (base + np < NN)       out[base + np]       = s0;
            if (base + np + 128 < NN) out[base + np + 128] = s1;
        }

        // ---- k / q / vw heads ----
        #pragma unroll 1
        for (int h = 0; h < 3; h++) {
            unsigned long long a2[16];
            {
                const unsigned long long* hp =
                    (const unsigned long long*)(bb + 64 + h * 64 + fh * 16);
                #pragma unroll
                for (int k = 0; k < 2; k++)
                    #pragma unroll
                    for (int j = 0; j < 8; j++) a2[k * 8 + j] = hp[j];
            }
            const float* ah = at + h * 4096 + fh * 16;
            for (int l = 0; l < 64; l++) {
                const float* hr = hs + l * 256 + np;
                unsigned long long h0, h1;
                PACK_DUP_F32X2(h0, hr[0]);
                PACK_DUP_F32X2(h1, hr[128]);
                const ulonglong2* wr = (const ulonglong2*)(ah + l * 64);
                { ulonglong2 w = wr[0]; STEP2(a2, 0, w, h0, h1); }
                { ulonglong2 w = wr[1]; STEP2(a2, 2, w, h0, h1); }
                { ulonglong2 w = wr[2]; STEP2(a2, 4, w, h0, h1); }
                { ulonglong2 w = wr[3]; STEP2(a2, 6, w, h0, h1); }
            }
            __nv_bfloat16* dp = (h == 0) ? g_kh : (h == 1) ? g_qh : g_vh;
            #pragma unroll
            for (int k = 0; k < 2; k++) {
                int node = base + np + 128 * k;
                if (node < NN) {
                    uint4 u;
                    float a0, a1, b0, b1, c0, c0b, d0, d1;
                    UNPACK_F32X2(a0, a1, a2[k * 8 + 0]);
                    UNPACK_F32X2(b0, b1, a2[k * 8 + 1]);
                    UNPACK_F32X2(c0, c0b, a2[k * 8 + 2]);
                    UNPACK_F32X2(d0, d1, a2[k * 8 + 3]);
                    u.x = pack_bf2(a0, a1); u.y = pack_bf2(b0, b1);
                    u.z = pack_bf2(c0, c0b); u.w = pack_bf2(d0, d1);
                    *(uint4*)(dp + (size_t)node * 64 + fh * 16) = u;
                    UNPACK_F32X2(a0, a1, a2[k * 8 + 4]);
                    UNPACK_F32X2(b0, b1, a2[k * 8 + 5]);
                    UNPACK_F32X2(c0, c0b, a2[k * 8 + 6]);
                    UNPACK_F32X2(d0, d1, a2[k * 8 + 7]);
                    u.x = pack_bf2(a0, a1); u.y = pack_bf2(b0, b1);
                    u.z = pack_bf2(c0, c0b); u.w = pack_bf2(d0, d1);
                    *(uint4*)(dp + (size_t)node * 64 + fh * 16 + 8) = u;
                }
            }
        }
    }
}

// ---------------- edge kernel: 4 lanes/edge, bf16 (measured 50us) ----------------
__device__ __forceinline__ float sigf(float x) {
    float t;
    asm("tanh.approx.f32 %0, %1;" : "=f"(t) : "f"(x * 0.5f));
    return fmaf(t, 0.5f, 0.5f);
}
__device__ __forceinline__ float2 bf2f(unsigned u) {
    __nv_bfloat162 h = *reinterpret_cast<__nv_bfloat162*>(&u);
    return __bfloat1622float2(h);
}
__device__ __forceinline__ float edge8(uint4 kk, uint4 qq, uint4 vv) {
    float s = 0.f;
    {
        float2 kf = bf2f(kk.x), qf = bf2f(qq.x), vf = bf2f(vv.x);
        s += sigf(kf.x + qf.x) * vf.x + sigf(kf.y + qf.y) * vf.y;
    }
    {
        float2 kf = bf2f(kk.y), qf = bf2f(qq.y), vf = bf2f(vv.y);
        s += sigf(kf.x + qf.x) * vf.x + sigf(kf.y + qf.y) * vf.y;
    }
    {
        float2 kf = bf2f(kk.z), qf = bf2f(qq.z), vf = bf2f(vv.z);
        s += sigf(kf.x + qf.x) * vf.x + sigf(kf.y + qf.y) * vf.y;
    }
    {
        float2 kf = bf2f(kk.w), qf = bf2f(qq.w), vf = bf2f(vv.w);
        s += sigf(kf.x + qf.x) * vf.x + sigf(kf.y + qf.y) * vf.y;
    }
    return s;
}

__global__ __launch_bounds__(256)
void edge_kernel(const int* __restrict__ ei, float* __restrict__ out)
{
    int t = blockIdx.x * 256 + threadIdx.x;
    int e = t >> 2;
    if (e >= EE) return;
    int sub = t & 3;

    int src = ei[e];
    int dst = ei[EE + e];

    const uint4* kp = (const uint4*)(g_kh + (size_t)dst * 64 + sub * 16);
    const uint4* qp = (const uint4*)(g_qh + (size_t)src * 64 + sub * 16);
    const uint4* vp = (const uint4*)(g_vh + (size_t)src * 64 + sub * 16);
    uint4 k0 = kp[0], k1 = kp[1];
    uint4 q0 = qp[0], q1 = qp[1];
    uint4 v0 = vp[0], v1 = vp[1];

    float s = edge8(k0, q0, v0) + edge8(k1, q1, v1);

    s += __shfl_down_sync(0xffffffffu, s, 2, 4);
    s += __shfl_down_sync(0xffffffffu, s, 1, 4);
    if (sub == 0) atomicAdd(out + dst, s);
}

extern "C" void kernel_launch(void* const* d_in, const int* in_sizes, int n_in,
                              void* d_out, int out_size)
{
    const float* x      = (const float*)d_in[0];
    const int*   ei     = (const int*)d_in[1];
    const float* W1     = (const float*)d_in[2];
    const float* b1     = (const float*)d_in[3];
    const float* W2     = (const float*)d_in[4];
    const float* b2     = (const float*)d_in[5];
    const float* Wk     = (const float*)d_in[6];
    const float* bk     = (const float*)d_in[7];
    const float* Wq     = (const float*)d_in[8];
    const float* bq     = (const float*)d_in[9];
    const float* Wv     = (const float*)d_in[10];
    const float* bv     = (const float*)d_in[11];
    const float* Ws     = (const float*)d_in[12];
    const float* b_gate = (const float*)d_in[13];
    const float* Wsc    = (const float*)d_in[14];
    const float* bsc    = (const float*)d_in[15];
    float* out = (float*)d_out;

    size_t smemf = (12288 + 8192 + 320 + 32 * 257 + 64 * 256) * sizeof(float);  // ~177.4 KB
    cudaFuncSetAttribute(node_fused, cudaFuncAttributeMaxDynamicSharedMemorySize, (int)smemf);

    prec1<<<49, 256>>>(W2, b2, Wk, bk, Wq, bq, Wv, bv, Ws, b_gate, Wsc, bsc);
    node_fused<<<148, 512, smemf>>>(x, W1, b1, out);
    edge_kernel<<<(EE * 4) / 256, 256>>>(ei, out);
}

// round 9
// speedup vs baseline: 1.3655x; 1.3655x over previous
#include <cuda_runtime.h>
#include <cuda_bf16.h>

#define NN 100000
#define EE 1600000
#define NT 391            // node tiles of 256

#define FMA_F32X2(d, a, b, c) \
    asm("fma.rn.f32x2 %0, %1, %2, %3;" : "=l"(d) : "l"(a), "l"(b), "l"(c))
#define PACK_DUP_F32X2(out, f) do { \
    unsigned _u = __float_as_uint(f); \
    asm("mov.b64 %0, {%1, %1};" : "=l"(out) : "r"(_u)); } while (0)
#define UNPACK_F32X2(lo, hi, in) \
    asm("mov.b64 {%0, %1}, %2;" : "=f"(lo), "=f"(hi) : "l"(in))

// 2 nodes x one ulonglong2 weight pair -> 4 FFMA2
#define STEP2(acc, J, w, h0, h1) do { \
    FMA_F32X2(acc[(J)],     h0, (w).x, acc[(J)]); \
    FMA_F32X2(acc[(J)+1],   h0, (w).y, acc[(J)+1]); \
    FMA_F32X2(acc[8+(J)],   h1, (w).x, acc[8+(J)]); \
    FMA_F32X2(acc[8+(J)+1], h1, (w).y, acc[8+(J)+1]); } while (0)

// ---- device scratch (no allocation) ----
__device__ float g_At[3 * 64 * 64];             // composed head weights [h][l][i]
__device__ float g_bh[3 * 64];                  // composed head biases
__device__ float g_u1[64];                      // W2^T Ws^T wsc
__device__ float g_c1;
__device__ __nv_bfloat16 g_kh[(size_t)NN * 64];
__device__ __nv_bfloat16 g_qh[(size_t)NN * 64];
__device__ __nv_bfloat16 g_vh[(size_t)NN * 64];

// ---------------- prologue: compose weights (parallel, 4 blocks) ----------------
__global__ __launch_bounds__(256)
void prec(const float* __restrict__ W2, const float* __restrict__ b2,
          const float* __restrict__ Wk, const float* __restrict__ bk,
          const float* __restrict__ Wq, const float* __restrict__ bq,
          const float* __restrict__ Wv, const float* __restrict__ bv,
          const float* __restrict__ Ws, const float* __restrict__ b_gate,
          const float* __restrict__ Wsc, const float* __restrict__ bsc)
{
    const int tid = threadIdx.x;
    const int blk = blockIdx.x;

    if (blk < 3) {
        // At[blk][l][i] = sum_j Wh[i*64+j] * W2[j*64+l]   (× Wsc[i] for blk==2)
        __shared__ float wht[4096];   // Wh transposed: wht[j*64+i] = Wh[i*64+j]
        __shared__ float w2s[4096];   // W2 RAW: w2s[idx] = W2[idx]  (access w2s[j*64+l])
        __shared__ float wscs[64];
        const float* Wh = blk == 0 ? Wk : blk == 1 ? Wq : Wv;
        for (int idx = tid; idx < 4096; idx += 256) {
            int r = idx >> 6, c = idx & 63;
            wht[c * 64 + r] = Wh[idx];   // transpose Wh
            w2s[idx]        = W2[idx];   // raw W2
        }
        if (tid < 64) wscs[tid] = Wsc[tid];
        __syncthreads();

        const int i = tid & 63;
        const int lbase = tid >> 6;                  // 0..3
        float accs[16];
        #pragma unroll
        for (int t = 0; t < 16; t++) accs[t] = 0.f;
        for (int j = 0; j < 64; j++) {
            float wv = wht[j * 64 + i];
            #pragma unroll
            for (int t = 0; t < 16; t++)
                accs[t] = fmaf(wv, w2s[j * 64 + lbase + 4 * t], accs[t]);
        }
        float scale = (blk == 2) ? wscs[i] : 1.f;
        #pragma unroll
        for (int t = 0; t < 16; t++) {
            int l = lbase + 4 * t;
            g_At[blk * 4096 + l * 64 + i] = accs[t] * scale;
        }
    } else {
        // biases, u1, c1
        __shared__ float ul[64];
        if (tid < 64) {
            float s = 0.f;
            for (int j = 0; j < 64; j++) s = fmaf(Wsc[j], Ws[j * 64 + tid], s);
            ul[tid] = s;
        }
        __syncthreads();
        if (tid < 64) {
            int i = tid;
            float sk = bk[i], sq = bq[i], sv = bv[i], u1 = 0.f;
            for (int j = 0; j < 64; j++) {
                float b2j = b2[j];
                sk = fmaf(Wk[i * 64 + j], b2j, sk);
                sq = fmaf(Wq[i * 64 + j], b2j, sq);
                sv = fmaf(Wv[i * 64 + j], b2j, sv);
                u1 = fmaf(ul[j], W2[j * 64 + i], u1);
            }
            g_bh[i] = sk; g_bh[64 + i] = sq; g_bh[128 + i] = sv * Wsc[i];
            g_u1[i] = u1;
            if (i == 0) {
                float c = bsc[0];
                for (int j = 0; j < 64; j++) c = fmaf(Wsc[j], b_gate[j], c);
                for (int l = 0; l < 64; l++) c = fmaf(ul[l], b2[l], c);
                g_c1 = c;
            }
        }
    }
}

__device__ __forceinline__ unsigned pack_bf2(float a, float b) {
    __nv_bfloat162 h = __floats2bfloat162_rn(a, b);
    return *reinterpret_cast<unsigned*>(&h);
}

// ---------------- fused persistent node kernel ----------------
__global__ __launch_bounds__(512, 1)
void node_fused(const float* __restrict__ x,
                const float* __restrict__ W1, const float* __restrict__ b1,
                float* __restrict__ out)
{
    extern __shared__ float sm[];
    float* at  = sm;               // 12288
    float* w1t = at + 12288;       // 8192 : [i=128][j=64]
    float* bb  = w1t + 8192;       // 320 : b1(64) | bh(192) | u1(64)
    float* xs  = bb + 320;         // 32 * 257
    float* hs  = xs + 32 * 257;    // 64 * 256

    const int tid = threadIdx.x;

    for (int idx = tid; idx < 8192; idx += 512) {
        int j = idx >> 7, i = idx & 127;
        w1t[i * 64 + j] = W1[idx];
    }
    for (int idx = tid; idx < 3072; idx += 512)
        ((float4*)at)[idx] = ((const float4*)g_At)[idx];
    if (tid < 64)       bb[tid] = b1[tid];
    else if (tid < 256) bb[tid] = g_bh[tid - 64];
    else if (tid < 320) bb[tid] = g_u1[tid - 256];
    const float c1 = g_c1;
    __syncthreads();

    const int fh = tid >> 7;       // 0..3
    const int np = tid & 127;      // 0..127

    for (int tile = blockIdx.x; tile < NT; tile += gridDim.x) {
        const int base = tile * 256;

        unsigned long long acc2[16];
        {
            const unsigned long long* bp = (const unsigned long long*)(bb + fh * 16);
            #pragma unroll
            for (int k = 0; k < 2; k++)
                #pragma unroll
                for (int j = 0; j < 8; j++) acc2[k * 8 + j] = bp[j];
        }

        for (int c = 0; c < 4; c++) {
            __syncthreads();
            #pragma unroll
            for (int idx = tid; idx < 2048; idx += 512) {
                int n = idx >> 3, i4 = idx & 7;
                int nn = base + n;
                float4 v = (nn < NN) ? ((const float4*)x)[(size_t)nn * 32 + c * 8 + i4]
                                     : make_float4(0.f, 0.f, 0.f, 0.f);
                xs[(i4 * 4 + 0) * 257 + n] = v.x;
                xs[(i4 * 4 + 1) * 257 + n] = v.y;
                xs[(i4 * 4 + 2) * 257 + n] = v.z;
                xs[(i4 * 4 + 3) * 257 + n] = v.w;
            }
            __syncthreads();
            const float* wbase = w1t + c * 2048 + fh * 16;
            for (int i = 0; i < 32; i++) {
                const float* xr = xs + i * 257 + np;
                unsigned long long h0, h1;
                PACK_DUP_F32X2(h0, xr[0]);
                PACK_DUP_F32X2(h1, xr[128]);
                const ulonglong2* wr = (const ulonglong2*)(wbase + i * 64);
                { ulonglong2 w = wr[0]; STEP2(acc2, 0, w, h0, h1); }
                { ulonglong2 w = wr[1]; STEP2(acc2, 2, w, h0, h1); }
                { ulonglong2 w = wr[2]; STEP2(acc2, 4, w, h0, h1); }
                { ulonglong2 w = wr[3]; STEP2(acc2, 6, w, h0, h1); }
            }
        }

        #pragma unroll
        for (int k = 0; k < 2; k++) {
            int n = np + 128 * k;
            #pragma unroll
            for (int j = 0; j < 8; j++) {
                float lo, hi;
                UNPACK_F32X2(lo, hi, acc2[k * 8 + j]);
                hs[(fh * 16 + 2 * j + 0) * 256 + n] = fmaxf(lo, 0.f);
                hs[(fh * 16 + 2 * j + 1) * 256 + n] = fmaxf(hi, 0.f);
            }
        }
        __syncthreads();

        if (fh == 0) {
            float s0 = c1, s1 = c1;
            #pragma unroll 4
            for (int l = 0; l < 64; l++) {
                float ul = bb[256 + l];
                const float* hr = hs + l * 256 + np;
                s0 = fmaf(hr[0],   ul, s0);
                s1 = fmaf(hr[128], ul, s1);
            }
            if (base + np < NN)       out[base + np]       = s0;
            if (base + np + 128 < NN) out[base + np + 128] = s1;
        }

        #pragma unroll 1
        for (int h = 0; h < 3; h++) {
            unsigned long long a2[16];
            {
                const unsigned long long* hp =
                    (const unsigned long long*)(bb + 64 + h * 64 + fh * 16);
                #pragma unroll
                for (int k = 0; k < 2; k++)
                    #pragma unroll
                    for (int j = 0; j < 8; j++) a2[k * 8 + j] = hp[j];
            }
            const float* ah = at + h * 4096 + fh * 16;
            for (int l = 0; l < 64; l++) {
                const float* hr = hs + l * 256 + np;
                unsigned long long h0, h1;
                PACK_DUP_F32X2(h0, hr[0]);
                PACK_DUP_F32X2(h1, hr[128]);
                const ulonglong2* wr = (const ulonglong2*)(ah + l * 64);
                { ulonglong2 w = wr[0]; STEP2(a2, 0, w, h0, h1); }
                { ulonglong2 w = wr[1]; STEP2(a2, 2, w, h0, h1); }
                { ulonglong2 w = wr[2]; STEP2(a2, 4, w, h0, h1); }
                { ulonglong2 w = wr[3]; STEP2(a2, 6, w, h0, h1); }
            }
            __nv_bfloat16* dp = (h == 0) ? g_kh : (h == 1) ? g_qh : g_vh;
            #pragma unroll
            for (int k = 0; k < 2; k++) {
                int node = base + np + 128 * k;
                if (node < NN) {
                    uint4 u;
                    float a0, a1, b0, b1, c0, c0b, d0, d1;
                    UNPACK_F32X2(a0, a1, a2[k * 8 + 0]);
                    UNPACK_F32X2(b0, b1, a2[k * 8 + 1]);
                    UNPACK_F32X2(c0, c0b, a2[k * 8 + 2]);
                    UNPACK_F32X2(d0, d1, a2[k * 8 + 3]);
                    u.x = pack_bf2(a0, a1); u.y = pack_bf2(b0, b1);
                    u.z = pack_bf2(c0, c0b); u.w = pack_bf2(d0, d1);
                    *(uint4*)(dp + (size_t)node * 64 + fh * 16) = u;
                    UNPACK_F32X2(a0, a1, a2[k * 8 + 4]);
                    UNPACK_F32X2(b0, b1, a2[k * 8 + 5]);
                    UNPACK_F32X2(c0, c0b, a2[k * 8 + 6]);
                    UNPACK_F32X2(d0, d1, a2[k * 8 + 7]);
                    u.x = pack_bf2(a0, a1); u.y = pack_bf2(b0, b1);
                    u.z = pack_bf2(c0, c0b); u.w = pack_bf2(d0, d1);
                    *(uint4*)(dp + (size_t)node * 64 + fh * 16 + 8) = u;
                }
            }
        }
    }
}

// ---------------- edge kernel: 4 lanes/edge, bf16 (measured 50us) ----------------
__device__ __forceinline__ float sigf(float x) {
    float t;
    asm("tanh.approx.f32 %0, %1;" : "=f"(t) : "f"(x * 0.5f));
    return fmaf(t, 0.5f, 0.5f);
}
__device__ __forceinline__ float2 bf2f(unsigned u) {
    __nv_bfloat162 h = *reinterpret_cast<__nv_bfloat162*>(&u);
    return __bfloat1622float2(h);
}
__device__ __forceinline__ float edge8(uint4 kk, uint4 qq, uint4 vv) {
    float s = 0.f;
    {
        float2 kf = bf2f(kk.x), qf = bf2f(qq.x), vf = bf2f(vv.x);
        s += sigf(kf.x + qf.x) * vf.x + sigf(kf.y + qf.y) * vf.y;
    }
    {
        float2 kf = bf2f(kk.y), qf = bf2f(qq.y), vf = bf2f(vv.y);
        s += sigf(kf.x + qf.x) * vf.x + sigf(kf.y + qf.y) * vf.y;
    }
    {
        float2 kf = bf2f(kk.z), qf = bf2f(qq.z), vf = bf2f(vv.z);
        s += sigf(kf.x + qf.x) * vf.x + sigf(kf.y + qf.y) * vf.y;
    }
    {
        float2 kf = bf2f(kk.w), qf = bf2f(qq.w), vf = bf2f(vv.w);
        s += sigf(kf.x + qf.x) * vf.x + sigf(kf.y + qf.y) * vf.y;
    }
    return s;
}

__global__ __launch_bounds__(256)
void edge_kernel(const int* __restrict__ ei, float* __restrict__ out)
{
    int t = blockIdx.x * 256 + threadIdx.x;
    int e = t >> 2;
    if (e >= EE) return;
    int sub = t & 3;

    int src = ei[e];
    int dst = ei[EE + e];

    const uint4* kp = (const uint4*)(g_kh + (size_t)dst * 64 + sub * 16);
    const uint4* qp = (const uint4*)(g_qh + (size_t)src * 64 + sub * 16);
    const uint4* vp = (const uint4*)(g_vh + (size_t)src * 64 + sub * 16);
    uint4 k0 = kp[0], k1 = kp[1];
    uint4 q0 = qp[0], q1 = qp[1];
    uint4 v0 = vp[0], v1 = vp[1];

    float s = edge8(k0, q0, v0) + edge8(k1, q1, v1);

    s += __shfl_down_sync(0xffffffffu, s, 2, 4);
    s += __shfl_down_sync(0xffffffffu, s, 1, 4);
    if (sub == 0) atomicAdd(out + dst, s);
}

extern "C" void kernel_launch(void* const* d_in, const int* in_sizes, int n_in,
                              void* d_out, int out_size)
{
    const float* x      = (const float*)d_in[0];
    const int*   ei     = (const int*)d_in[1];
    const float* W1     = (const float*)d_in[2];
    const float* b1     = (const float*)d_in[3];
    const float* W2     = (const float*)d_in[4];
    const float* b2     = (const float*)d_in[5];
    const float* Wk     = (const float*)d_in[6];
    const float* bk     = (const float*)d_in[7];
    const float* Wq     = (const float*)d_in[8];
    const float* bq     = (const float*)d_in[9];
    const float* Wv     = (const float*)d_in[10];
    const float* bv     = (const float*)d_in[11];
    const float* Ws     = (const float*)d_in[12];
    const float* b_gate = (const float*)d_in[13];
    const float* Wsc    = (const float*)d_in[14];
    const float* bsc    = (const float*)d_in[15];
    float* out = (float*)d_out;

    size_t smemf = (12288 + 8192 + 320 + 32 * 257 + 64 * 256) * sizeof(float);  // ~177.4 KB
    cudaFuncSetAttribute(node_fused, cudaFuncAttributeMaxDynamicSharedMemorySize, (int)smemf);

    prec<<<4, 256>>>(W2, b2, Wk, bk, Wq, bq, Wv, bv, Ws, b_gate, Wsc, bsc);
    node_fused<<<148, 512, smemf>>>(x, W1, b1, out);
    edge_kernel<<<(EE * 4) / 256, 256>>>(ei, out);
}